// round 14
// baseline (speedup 1.0000x reference)
#include <cuda_runtime.h>
#include <cuda_fp16.h>
#include <cstdint>
#include <math.h>

#define NT 8192
#define DD 1024
#define FF 4096
#define NE 8
#define BM 128
#define BK 64
#define BN2 128
#define MAX_ROWS (NT*2 + NE*BM)   // 17408
#define MT (MAX_ROWS/BM)          // 136
#define GROUP 16
#define MTP (((MT+GROUP-1)/GROUP)*GROUP)   // 144

#define PITCH 72                     // halves per smem row (144B)

// ffn1 (512 threads): A 128 rows, B 256 rows (2 mats x 128 cols)
#define STA1_H (128*PITCH)           // 9216
#define STB1_H (256*PITCH)           // 18432
#define STG1_H (STA1_H + STB1_H)     // 27648
#define NSTAGE 3
#define SMEM1_BYTES (NSTAGE * STG1_H * 2)   // 165888

// ffn2 (256 threads): unchanged champion config
#define STA2_H (128*PITCH)
#define STB2_H (128*PITCH)
#define STG2_H (STA2_H + STB2_H)
#define SMEM2_BYTES (NSTAGE * STG2_H * 2)   // 110592

__device__ __align__(128) __half g_h[(size_t)MAX_ROWS * FF];
__device__ __align__(128) __half g_xh[(size_t)MAX_ROWS * DD];
__device__ __align__(128) __half g_w1t[(size_t)NE * FF * DD];
__device__ __align__(128) __half g_w3t[(size_t)NE * FF * DD];
__device__ __align__(128) __half g_w2t[(size_t)NE * DD * FF];
__device__ __align__(128) float  g_o[(size_t)MAX_ROWS * DD];
__device__ __align__(128) float  g_gwt[NE * DD];
__device__ int   g_perm[MAX_ROWS];
__device__ float g_wt[MAX_ROWS];
__device__ int   g_tpos[NT * 2];
__device__ int   g_counts[NE];
__device__ int   g_offs[NE + 1];
__device__ int   g_cursor[NE];
__device__ int   g_eid[NT * 2];
__device__ float g_wr[NT * 2];

__device__ __forceinline__ void mma_f16(float c[4], const uint32_t a[4], const uint32_t b0, const uint32_t b1) {
    asm volatile(
        "mma.sync.aligned.m16n8k16.row.col.f32.f16.f16.f32 "
        "{%0,%1,%2,%3}, {%4,%5,%6,%7}, {%8,%9}, {%0,%1,%2,%3};\n"
        : "+f"(c[0]), "+f"(c[1]), "+f"(c[2]), "+f"(c[3])
        : "r"(a[0]), "r"(a[1]), "r"(a[2]), "r"(a[3]), "r"(b0), "r"(b1));
}
__device__ __forceinline__ void ldsm4(uint32_t r[4], uint32_t addr) {
    asm volatile("ldmatrix.sync.aligned.m8n8.x4.shared.b16 {%0,%1,%2,%3}, [%4];"
                 : "=r"(r[0]), "=r"(r[1]), "=r"(r[2]), "=r"(r[3]) : "r"(addr));
}
__device__ __forceinline__ void cp16(uint32_t dst, const void* src) {
    asm volatile("cp.async.cg.shared.global [%0], [%1], 16;\n" :: "r"(dst), "l"(src));
}
#define CP_COMMIT() asm volatile("cp.async.commit_group;\n")
#define CP_WAIT1()  asm volatile("cp.async.wait_group 1;\n")
#define CP_WAIT0()  asm volatile("cp.async.wait_group 0;\n")

// ---------------------------------------------------------------------------
__global__ void init_kernel() {
    int idx = blockIdx.x * blockDim.x + threadIdx.x;
    int stride = gridDim.x * blockDim.x;
    for (int i = idx; i < MAX_ROWS; i += stride) g_perm[i] = -1;
    if (idx < NE) g_counts[idx] = 0;
}

__global__ void transpose_gw_kernel(const float* __restrict__ gw) {
    int idx = blockIdx.x * blockDim.x + threadIdx.x;
    if (idx >= NE * DD) return;
    int d = idx >> 3, e = idx & 7;
    g_gwt[e * DD + d] = gw[idx];
}

__global__ void router_kernel(const float* __restrict__ x) {
    int warp = (blockIdx.x * blockDim.x + threadIdx.x) >> 5;
    int lane = threadIdx.x & 31;
    if (warp >= NT) return;
    const float4* xr = reinterpret_cast<const float4*>(x + (size_t)warp * DD);
    float4 xv[8];
#pragma unroll
    for (int i = 0; i < 8; i++) xv[i] = xr[i * 32 + lane];

    float acc[NE];
#pragma unroll
    for (int e = 0; e < NE; e++) {
        const float4* gr = reinterpret_cast<const float4*>(g_gwt + e * DD);
        float s = 0.f;
#pragma unroll
        for (int i = 0; i < 8; i++) {
            float4 g = gr[i * 32 + lane];
            s += xv[i].x * g.x + xv[i].y * g.y + xv[i].z * g.z + xv[i].w * g.w;
        }
        acc[e] = s;
    }
#pragma unroll
    for (int e = 0; e < NE; e++)
#pragma unroll
        for (int o = 16; o > 0; o >>= 1)
            acc[e] += __shfl_xor_sync(0xFFFFFFFFu, acc[e], o);
    if (lane == 0) {
        int i0 = 0; float v0 = acc[0];
#pragma unroll
        for (int e = 1; e < NE; e++) if (acc[e] > v0) { v0 = acc[e]; i0 = e; }
        int i1 = -1; float v1 = -1e30f;
#pragma unroll
        for (int e = 0; e < NE; e++) {
            if (e == i0) continue;
            if (acc[e] > v1) { v1 = acc[e]; i1 = e; }
        }
        float e1 = expf(v1 - v0);
        float inv = 1.f / (1.f + e1);
        g_eid[2 * warp + 0] = i0; g_wr[2 * warp + 0] = inv;
        g_eid[2 * warp + 1] = i1; g_wr[2 * warp + 1] = e1 * inv;
        atomicAdd(&g_counts[i0], 1);
        atomicAdd(&g_counts[i1], 1);
    }
}

__global__ void offsets_kernel() {
    int acc = 0;
    for (int e = 0; e < NE; e++) {
        g_offs[e] = acc; g_cursor[e] = acc;
        acc += (g_counts[e] + BM - 1) / BM * BM;
    }
    g_offs[NE] = acc;
}

__global__ void scatter_kernel() {
    int t = blockIdx.x * blockDim.x + threadIdx.x;
    if (t >= NT) return;
#pragma unroll
    for (int k = 0; k < 2; k++) {
        int e = g_eid[2 * t + k];
        int pos = atomicAdd(&g_cursor[e], 1);
        g_perm[pos] = t;
        g_wt[pos] = g_wr[2 * t + k];
        g_tpos[2 * t + k] = pos;
    }
}

__global__ void gather_half_kernel(const float* __restrict__ x) {
    const int NC8 = DD / 8;
    int idx = blockIdx.x * blockDim.x + threadIdx.x;
    int stride = gridDim.x * blockDim.x;
    for (int i = idx; i < MAX_ROWS * NC8; i += stride) {
        int r = i / NC8, c8 = i % NC8;
        int p = g_perm[r];
        union { uint4 u; __half2 h[4]; } pk;
        if (p >= 0) {
            const float4* xs = reinterpret_cast<const float4*>(x + (size_t)p * DD + c8 * 8);
            float4 v0 = xs[0], v1 = xs[1];
            pk.h[0] = __floats2half2_rn(v0.x, v0.y);
            pk.h[1] = __floats2half2_rn(v0.z, v0.w);
            pk.h[2] = __floats2half2_rn(v1.x, v1.y);
            pk.h[3] = __floats2half2_rn(v1.z, v1.w);
        } else {
            pk.u = make_uint4(0, 0, 0, 0);
        }
        reinterpret_cast<uint4*>(g_xh)[(size_t)r * NC8 + c8] = pk.u;
    }
}

__global__ void transpose_w13_kernel(const float* __restrict__ w1,
                                     const float* __restrict__ w3) {
    __shared__ float s[32][33];
    int z = blockIdx.y, m = z >> 3, e = z & 7;
    const float* src = (m ? w3 : w1) + (size_t)e * DD * FF;
    __half* dst = (m ? g_w3t : g_w1t) + (size_t)e * FF * DD;
    const int R = DD, C = FF;
    int tpc = C / 32;
    int r0 = (blockIdx.x / tpc) * 32, c0 = (blockIdx.x % tpc) * 32;
    int rr = threadIdx.x >> 5, cc = threadIdx.x & 31;
#pragma unroll
    for (int i = 0; i < 4; i++)
        s[rr + 8 * i][cc] = src[(size_t)(r0 + rr + 8 * i) * C + c0 + cc];
    __syncthreads();
#pragma unroll
    for (int i = 0; i < 4; i++)
        dst[(size_t)(c0 + rr + 8 * i) * R + r0 + cc] = __float2half_rn(s[cc][rr + 8 * i]);
}

__global__ void transpose_w2_kernel(const float* __restrict__ w2) {
    __shared__ float s[32][33];
    int e = blockIdx.y;
    const float* src = w2 + (size_t)e * FF * DD;
    __half* dst = g_w2t + (size_t)e * DD * FF;
    const int R = FF, C = DD;
    int tpc = C / 32;
    int r0 = (blockIdx.x / tpc) * 32, c0 = (blockIdx.x % tpc) * 32;
    int rr = threadIdx.x >> 5, cc = threadIdx.x & 31;
#pragma unroll
    for (int i = 0; i < 4; i++)
        s[rr + 8 * i][cc] = src[(size_t)(r0 + rr + 8 * i) * C + c0 + cc];
    __syncthreads();
#pragma unroll
    for (int i = 0; i < 4; i++)
        dst[(size_t)(c0 + rr + 8 * i) * R + r0 + cc] = __float2half_rn(s[cc][rr + 8 * i]);
}

// ---------------------------------------------------------------------------
// FFN1: 512 threads, tile M=128 x N=128 per mat (W1+W3 both). Warp 32x32/mat.
__global__ __launch_bounds__(512, 1) void ffn1_kernel() {
    extern __shared__ __half smem_h[];

    const int NBT = FF / 128;  // 32
    int bid = blockIdx.x;
    int tm = (bid / (GROUP * NBT)) * GROUP + (bid % GROUP);
    int nb = (bid % (GROUP * NBT)) / GROUP;
    if (tm >= MT) return;
    const int r0 = tm * BM;
    if (r0 >= g_offs[NE]) return;
    const int n0 = nb * 128;

    int e = NE - 1;
#pragma unroll
    for (int i = 0; i < NE; i++)
        if (r0 >= g_offs[i] && r0 < g_offs[i + 1]) e = i;
    const __half* W1 = g_w1t + (size_t)e * FF * DD;
    const __half* W3 = g_w3t + (size_t)e * FF * DD;

    const int tid = threadIdx.x;
    const int lane = tid & 31, warp = tid >> 5;
    const int wm = (warp >> 2) * 32, wn = (warp & 3) * 32;
    const int grp = lane >> 2, qid = lane & 3;

    const int lrA = (lane & 7) + ((lane >> 3) & 1) * 8;
    const int kgA = (lane >> 4) * 8;
    const int lrB = (lane & 7) + ((lane >> 4) & 1) * 8;
    const int kgB = ((lane >> 3) & 1) * 8;

    uint32_t sm_u = (uint32_t)__cvta_generic_to_shared(smem_h);

    float acc1[2][4][4], acc3[2][4][4];
#pragma unroll
    for (int mi = 0; mi < 2; mi++)
#pragma unroll
        for (int ni = 0; ni < 4; ni++)
#pragma unroll
            for (int t = 0; t < 4; t++) { acc1[mi][ni][t] = 0.f; acc3[mi][ni][t] = 0.f; }

    const int NK = DD / BK;  // 16

    auto load_stage = [&](int slot, int k0) {
        uint32_t base = sm_u + slot * STG1_H * 2;
#pragma unroll
        for (int i = 0; i < 2; i++) {             // A: 1024 chunks / 512 threads
            int idx = tid + i * 512;
            int row = idx >> 3, c16 = (idx & 7) * 8;
            cp16(base + (row * PITCH + c16) * 2,
                 g_xh + (size_t)(r0 + row) * DD + k0 + c16);
        }
#pragma unroll
        for (int i = 0; i < 4; i++) {             // B: 2048 chunks (2 mats x 128 rows)
            int idx = tid + i * 512;
            int row = idx >> 3, c16 = (idx & 7) * 8;   // row 0..255
            int mat = row >> 7, nr = row & 127;
            const __half* W = mat ? W3 : W1;
            cp16(base + (STA1_H + row * PITCH + c16) * 2,
                 W + (size_t)(n0 + nr) * DD + k0 + c16);
        }
        CP_COMMIT();
    };

    load_stage(0, 0);
    load_stage(1, BK);

    for (int k = 0; k < NK; k++) {
        if (k + 1 < NK) CP_WAIT1(); else CP_WAIT0();
        __syncthreads();
        if (k + 2 < NK) load_stage((k + 2) % NSTAGE, (k + 2) * BK);

        int slot = k % NSTAGE;
        uint32_t Au = sm_u + slot * STG1_H * 2;
        uint32_t Bu = Au + STA1_H * 2;
#pragma unroll
        for (int c = 0; c < 4; c++) {
            int kc = c * 16;
            uint32_t a[2][4];
#pragma unroll
            for (int mi = 0; mi < 2; mi++)
                ldsm4(a[mi], Au + ((wm + mi * 16 + lrA) * PITCH + kc + kgA) * 2);
#pragma unroll
            for (int mat = 0; mat < 2; mat++) {
#pragma unroll
                for (int p = 0; p < 2; p++) {
                    uint32_t b[4];
                    ldsm4(b, Bu + ((mat * 128 + wn + p * 16 + lrB) * PITCH + kc + kgB) * 2);
#pragma unroll
                    for (int mi = 0; mi < 2; mi++) {
                        float* d0 = mat ? acc3[mi][p * 2 + 0] : acc1[mi][p * 2 + 0];
                        float* d1 = mat ? acc3[mi][p * 2 + 1] : acc1[mi][p * 2 + 1];
                        mma_f16(d0, a[mi], b[0], b[1]);
                        mma_f16(d1, a[mi], b[2], b[3]);
                    }
                }
            }
        }
    }

#pragma unroll
    for (int mi = 0; mi < 2; mi++)
#pragma unroll
        for (int ni = 0; ni < 4; ni++)
#pragma unroll
            for (int t2 = 0; t2 < 2; t2++) {
                int row = r0 + wm + mi * 16 + grp + t2 * 8;
                int col = n0 + wn + ni * 8 + qid * 2;
                float a0 = acc1[mi][ni][t2 * 2 + 0], a1 = acc1[mi][ni][t2 * 2 + 1];
                float s0 = a0 / (1.f + expf(-a0)) * acc3[mi][ni][t2 * 2 + 0];
                float s1 = a1 / (1.f + expf(-a1)) * acc3[mi][ni][t2 * 2 + 1];
                *reinterpret_cast<__half2*>(g_h + (size_t)row * FF + col) =
                    __floats2half2_rn(s0, s1);
            }
}

// ---------------------------------------------------------------------------
// FFN2: unchanged champion (256 threads, M=128 x N=128).
__global__ __launch_bounds__(256, 2) void ffn2_kernel() {
    extern __shared__ __half smem_h[];

    const int NBT = DD / BN2;  // 8
    int bid = blockIdx.x;
    int tm = (bid / (GROUP * NBT)) * GROUP + (bid % GROUP);
    int nb = (bid % (GROUP * NBT)) / GROUP;
    if (tm >= MT) return;
    const int r0 = tm * BM;
    if (r0 >= g_offs[NE]) return;
    const int n0 = nb * BN2;

    int e = NE - 1;
#pragma unroll
    for (int i = 0; i < NE; i++)
        if (r0 >= g_offs[i] && r0 < g_offs[i + 1]) e = i;
    const __half* W2 = g_w2t + (size_t)e * DD * FF;

    const int tid = threadIdx.x;
    const int lane = tid & 31, warp = tid >> 5;
    const int wm = (warp >> 1) * 32, wn = (warp & 1) * 64;
    const int grp = lane >> 2, qid = lane & 3;

    const int lrA = (lane & 7) + ((lane >> 3) & 1) * 8;
    const int kgA = (lane >> 4) * 8;
    const int lrB = (lane & 7) + ((lane >> 4) & 1) * 8;
    const int kgB = ((lane >> 3) & 1) * 8;

    uint32_t sm_u = (uint32_t)__cvta_generic_to_shared(smem_h);

    float acc[2][8][4];
#pragma unroll
    for (int mi = 0; mi < 2; mi++)
#pragma unroll
        for (int ni = 0; ni < 8; ni++)
#pragma unroll
            for (int t = 0; t < 4; t++) acc[mi][ni][t] = 0.f;

    const int NK = FF / BK;  // 64

    auto load_stage = [&](int slot, int k0) {
        uint32_t base = sm_u + slot * STG2_H * 2;
#pragma unroll
        for (int i = 0; i < 4; i++) {
            int idx = tid + i * 256;
            int row = idx >> 3, c16 = (idx & 7) * 8;
            cp16(base + (row * PITCH + c16) * 2,
                 g_h + (size_t)(r0 + row) * FF + k0 + c16);
        }
#pragma unroll
        for (int i = 0; i < 4; i++) {
            int idx = tid + i * 256;
            int row = idx >> 3, c16 = (idx & 7) * 8;
            cp16(base + (STA2_H + row * PITCH + c16) * 2,
                 W2 + (size_t)(n0 + row) * FF + k0 + c16);
        }
        CP_COMMIT();
    };

    load_stage(0, 0);
    load_stage(1, BK);

    for (int k = 0; k < NK; k++) {
        if (k + 1 < NK) CP_WAIT1(); else CP_WAIT0();
        __syncthreads();
        if (k + 2 < NK) load_stage((k + 2) % NSTAGE, (k + 2) * BK);

        int slot = k % NSTAGE;
        uint32_t Au = sm_u + slot * STG2_H * 2;
        uint32_t Bu = Au + STA2_H * 2;
#pragma unroll
        for (int c = 0; c < 4; c++) {
            int kc = c * 16;
            uint32_t a[2][4];
#pragma unroll
            for (int mi = 0; mi < 2; mi++)
                ldsm4(a[mi], Au + ((wm + mi * 16 + lrA) * PITCH + kc + kgA) * 2);
#pragma unroll
            for (int p = 0; p < 4; p++) {
                uint32_t b[4];
                ldsm4(b, Bu + ((wn + p * 16 + lrB) * PITCH + kc + kgB) * 2);
#pragma unroll
                for (int mi = 0; mi < 2; mi++) {
                    mma_f16(acc[mi][p * 2 + 0], a[mi], b[0], b[1]);
                    mma_f16(acc[mi][p * 2 + 1], a[mi], b[2], b[3]);
                }
            }
        }
    }

#pragma unroll
    for (int mi = 0; mi < 2; mi++) {
#pragma unroll
        for (int t2 = 0; t2 < 2; t2++) {
            int row = r0 + wm + mi * 16 + grp + t2 * 8;
            float* op = g_o + (size_t)row * DD + n0;
#pragma unroll
            for (int ni = 0; ni < 8; ni++) {
                float2 v = make_float2(acc[mi][ni][t2 * 2 + 0], acc[mi][ni][t2 * 2 + 1]);
                *reinterpret_cast<float2*>(op + wn + ni * 8 + qid * 2) = v;
            }
        }
    }
}

// ---------------------------------------------------------------------------
__global__ void combine_kernel(float* __restrict__ out) {
    const int NC4 = DD / 4;
    int idx = blockIdx.x * blockDim.x + threadIdx.x;
    int stride = gridDim.x * blockDim.x;
    for (int i = idx; i < NT * NC4; i += stride) {
        int t = i / NC4, c = i % NC4;
        int p0 = g_tpos[2 * t + 0], p1 = g_tpos[2 * t + 1];
        float w0 = g_wt[p0], w1 = g_wt[p1];
        float4 v0 = reinterpret_cast<const float4*>(g_o)[(size_t)p0 * NC4 + c];
        float4 v1 = reinterpret_cast<const float4*>(g_o)[(size_t)p1 * NC4 + c];
        float4 r;
        r.x = w0 * v0.x + w1 * v1.x;
        r.y = w0 * v0.y + w1 * v1.y;
        r.z = w0 * v0.z + w1 * v1.z;
        r.w = w0 * v0.w + w1 * v1.w;
        reinterpret_cast<float4*>(out)[i] = r;
    }
}

// ---------------------------------------------------------------------------
extern "C" void kernel_launch(void* const* d_in, const int* in_sizes, int n_in,
                              void* d_out, int out_size) {
    const float* x  = (const float*)d_in[0];
    const float* gw = (const float*)d_in[1];
    const float* w1 = (const float*)d_in[2];
    const float* w3 = (const float*)d_in[3];
    const float* w2 = (const float*)d_in[4];
    float* out = (float*)d_out;

    static cudaStream_t s_aux = nullptr;
    static cudaEvent_t ev_fork = nullptr, ev_w13 = nullptr, ev_w2 = nullptr;
    if (s_aux == nullptr) {
        cudaStreamCreateWithFlags(&s_aux, cudaStreamNonBlocking);
        cudaEventCreateWithFlags(&ev_fork, cudaEventDisableTiming);
        cudaEventCreateWithFlags(&ev_w13, cudaEventDisableTiming);
        cudaEventCreateWithFlags(&ev_w2, cudaEventDisableTiming);
        cudaFuncSetAttribute(ffn1_kernel, cudaFuncAttributeMaxDynamicSharedMemorySize, SMEM1_BYTES);
        cudaFuncSetAttribute(ffn2_kernel, cudaFuncAttributeMaxDynamicSharedMemorySize, SMEM2_BYTES);
    }

    cudaEventRecord(ev_fork, 0);
    cudaStreamWaitEvent(s_aux, ev_fork, 0);

    transpose_w13_kernel<<<dim3(4096, 16), 256, 0, s_aux>>>(w1, w3);
    cudaEventRecord(ev_w13, s_aux);
    transpose_w2_kernel<<<dim3(4096, 8), 256, 0, s_aux>>>(w2);
    cudaEventRecord(ev_w2, s_aux);

    init_kernel<<<256, 256>>>();
    transpose_gw_kernel<<<32, 256>>>(gw);
    router_kernel<<<NT / 8, 256>>>(x);
    offsets_kernel<<<1, 1>>>();
    scatter_kernel<<<(NT + 255) / 256, 256>>>();
    gather_half_kernel<<<4096, 256>>>(x);

    cudaStreamWaitEvent(0, ev_w13, 0);
    ffn1_kernel<<<MTP * (FF / 128), 512, SMEM1_BYTES>>>();
    cudaStreamWaitEvent(0, ev_w2, 0);
    ffn2_kernel<<<MTP * (DD / BN2), 256, SMEM2_BYTES>>>();
    combine_kernel<<<2048, 256>>>(out);
}

// round 15
// speedup vs baseline: 1.0707x; 1.0707x over previous
#include <cuda_runtime.h>
#include <cuda_fp16.h>
#include <cstdint>
#include <math.h>

#define NT 8192
#define DD 1024
#define FF 4096
#define NE 8
#define BM 128
#define BK 64
#define BN1 64
#define BN2 128
#define MAX_ROWS (NT*2 + NE*BM)   // 17408
#define MT (MAX_ROWS/BM)          // 136
#define GROUP 16
#define MTP (((MT+GROUP-1)/GROUP)*GROUP)   // 144

#define PITCH 72                     // halves per smem row (144B)
#define STA_H (BM*PITCH)             // 9216 halves
#define STB_H (128*PITCH)            // 9216 halves
#define STG_H (STA_H + STB_H)        // 18432 halves per stage
#define NSTAGE 3
#define SMEM_BYTES (NSTAGE * STG_H * 2)   // 110592

__device__ __align__(128) __half g_h[(size_t)MAX_ROWS * FF];
__device__ __align__(128) __half g_xh[(size_t)MAX_ROWS * DD];
__device__ __align__(128) __half g_w1t[(size_t)NE * FF * DD];
__device__ __align__(128) __half g_w3t[(size_t)NE * FF * DD];
__device__ __align__(128) __half g_w2t[(size_t)NE * DD * FF];
__device__ __align__(128) float  g_o[(size_t)MAX_ROWS * DD];
__device__ __align__(128) float  g_gwt[NE * DD];   // gate_w transposed [E][D]
__device__ int   g_perm[MAX_ROWS];
__device__ float g_wt[MAX_ROWS];
__device__ int   g_tpos[NT * 2];
__device__ int   g_counts[NE];
__device__ int   g_offs[NE + 1];
__device__ int   g_cursor[NE];
__device__ int   g_eid[NT * 2];
__device__ float g_wr[NT * 2];

__device__ __forceinline__ void mma_f16(float c[4], const uint32_t a[4], const uint32_t b0, const uint32_t b1) {
    asm volatile(
        "mma.sync.aligned.m16n8k16.row.col.f32.f16.f16.f32 "
        "{%0,%1,%2,%3}, {%4,%5,%6,%7}, {%8,%9}, {%0,%1,%2,%3};\n"
        : "+f"(c[0]), "+f"(c[1]), "+f"(c[2]), "+f"(c[3])
        : "r"(a[0]), "r"(a[1]), "r"(a[2]), "r"(a[3]), "r"(b0), "r"(b1));
}
__device__ __forceinline__ void ldsm4(uint32_t r[4], uint32_t addr) {
    asm volatile("ldmatrix.sync.aligned.m8n8.x4.shared.b16 {%0,%1,%2,%3}, [%4];"
                 : "=r"(r[0]), "=r"(r[1]), "=r"(r[2]), "=r"(r[3]) : "r"(addr));
}
__device__ __forceinline__ void cp16(uint32_t dst, const void* src) {
    asm volatile("cp.async.cg.shared.global [%0], [%1], 16;\n" :: "r"(dst), "l"(src));
}
#define CP_COMMIT() asm volatile("cp.async.commit_group;\n")
#define CP_WAIT1()  asm volatile("cp.async.wait_group 1;\n")
#define CP_WAIT0()  asm volatile("cp.async.wait_group 0;\n")

// Fast SwiGLU: x * sigmoid(x) * g, via MUFU-based __expf (err ~1e-6, far below
// the fp16 storage quantization of g_h).
__device__ __forceinline__ float swiglu(float a, float g) {
    return __fdividef(a, 1.f + __expf(-a)) * g;
}

// ---------------------------------------------------------------------------
__global__ void init_kernel() {
    int idx = blockIdx.x * blockDim.x + threadIdx.x;
    int stride = gridDim.x * blockDim.x;
    for (int i = idx; i < MAX_ROWS; i += stride) g_perm[i] = -1;
    if (idx < NE) g_counts[idx] = 0;
}

__global__ void transpose_gw_kernel(const float* __restrict__ gw) {
    int idx = blockIdx.x * blockDim.x + threadIdx.x;
    if (idx >= NE * DD) return;
    int d = idx >> 3, e = idx & 7;
    g_gwt[e * DD + d] = gw[idx];
}

__global__ void router_kernel(const float* __restrict__ x) {
    int warp = (blockIdx.x * blockDim.x + threadIdx.x) >> 5;
    int lane = threadIdx.x & 31;
    if (warp >= NT) return;
    const float4* xr = reinterpret_cast<const float4*>(x + (size_t)warp * DD);
    float4 xv[8];
#pragma unroll
    for (int i = 0; i < 8; i++) xv[i] = xr[i * 32 + lane];

    float acc[NE];
#pragma unroll
    for (int e = 0; e < NE; e++) {
        const float4* gr = reinterpret_cast<const float4*>(g_gwt + e * DD);
        float s = 0.f;
#pragma unroll
        for (int i = 0; i < 8; i++) {
            float4 g = gr[i * 32 + lane];
            s += xv[i].x * g.x + xv[i].y * g.y + xv[i].z * g.z + xv[i].w * g.w;
        }
        acc[e] = s;
    }
#pragma unroll
    for (int e = 0; e < NE; e++)
#pragma unroll
        for (int o = 16; o > 0; o >>= 1)
            acc[e] += __shfl_xor_sync(0xFFFFFFFFu, acc[e], o);
    if (lane == 0) {
        int i0 = 0; float v0 = acc[0];
#pragma unroll
        for (int e = 1; e < NE; e++) if (acc[e] > v0) { v0 = acc[e]; i0 = e; }
        int i1 = -1; float v1 = -1e30f;
#pragma unroll
        for (int e = 0; e < NE; e++) {
            if (e == i0) continue;
            if (acc[e] > v1) { v1 = acc[e]; i1 = e; }
        }
        float e1 = expf(v1 - v0);   // keep precise: routing weights feed output
        float inv = 1.f / (1.f + e1);
        g_eid[2 * warp + 0] = i0; g_wr[2 * warp + 0] = inv;
        g_eid[2 * warp + 1] = i1; g_wr[2 * warp + 1] = e1 * inv;
        atomicAdd(&g_counts[i0], 1);
        atomicAdd(&g_counts[i1], 1);
    }
}

__global__ void offsets_kernel() {
    int acc = 0;
    for (int e = 0; e < NE; e++) {
        g_offs[e] = acc; g_cursor[e] = acc;
        acc += (g_counts[e] + BM - 1) / BM * BM;
    }
    g_offs[NE] = acc;
}

__global__ void scatter_kernel() {
    int t = blockIdx.x * blockDim.x + threadIdx.x;
    if (t >= NT) return;
#pragma unroll
    for (int k = 0; k < 2; k++) {
        int e = g_eid[2 * t + k];
        int pos = atomicAdd(&g_cursor[e], 1);
        g_perm[pos] = t;
        g_wt[pos] = g_wr[2 * t + k];
        g_tpos[2 * t + k] = pos;
    }
}

__global__ void gather_half_kernel(const float* __restrict__ x) {
    const int NC8 = DD / 8;
    int idx = blockIdx.x * blockDim.x + threadIdx.x;
    int stride = gridDim.x * blockDim.x;
    for (int i = idx; i < MAX_ROWS * NC8; i += stride) {
        int r = i / NC8, c8 = i % NC8;
        int p = g_perm[r];
        union { uint4 u; __half2 h[4]; } pk;
        if (p >= 0) {
            const float4* xs = reinterpret_cast<const float4*>(x + (size_t)p * DD + c8 * 8);
            float4 v0 = xs[0], v1 = xs[1];
            pk.h[0] = __floats2half2_rn(v0.x, v0.y);
            pk.h[1] = __floats2half2_rn(v0.z, v0.w);
            pk.h[2] = __floats2half2_rn(v1.x, v1.y);
            pk.h[3] = __floats2half2_rn(v1.z, v1.w);
        } else {
            pk.u = make_uint4(0, 0, 0, 0);
        }
        reinterpret_cast<uint4*>(g_xh)[(size_t)r * NC8 + c8] = pk.u;
    }
}

__global__ void transpose_w13_kernel(const float* __restrict__ w1,
                                     const float* __restrict__ w3) {
    __shared__ float s[32][33];
    int z = blockIdx.y, m = z >> 3, e = z & 7;
    const float* src = (m ? w3 : w1) + (size_t)e * DD * FF;
    __half* dst = (m ? g_w3t : g_w1t) + (size_t)e * FF * DD;
    const int R = DD, C = FF;
    int tpc = C / 32;
    int r0 = (blockIdx.x / tpc) * 32, c0 = (blockIdx.x % tpc) * 32;
    int rr = threadIdx.x >> 5, cc = threadIdx.x & 31;
#pragma unroll
    for (int i = 0; i < 4; i++)
        s[rr + 8 * i][cc] = src[(size_t)(r0 + rr + 8 * i) * C + c0 + cc];
    __syncthreads();
#pragma unroll
    for (int i = 0; i < 4; i++)
        dst[(size_t)(c0 + rr + 8 * i) * R + r0 + cc] = __float2half_rn(s[cc][rr + 8 * i]);
}

__global__ void transpose_w2_kernel(const float* __restrict__ w2) {
    __shared__ float s[32][33];
    int e = blockIdx.y;
    const float* src = w2 + (size_t)e * FF * DD;
    __half* dst = g_w2t + (size_t)e * DD * FF;
    const int R = FF, C = DD;
    int tpc = C / 32;
    int r0 = (blockIdx.x / tpc) * 32, c0 = (blockIdx.x % tpc) * 32;
    int rr = threadIdx.x >> 5, cc = threadIdx.x & 31;
#pragma unroll
    for (int i = 0; i < 4; i++)
        s[rr + 8 * i][cc] = src[(size_t)(r0 + rr + 8 * i) * C + c0 + cc];
    __syncthreads();
#pragma unroll
    for (int i = 0; i < 4; i++)
        dst[(size_t)(c0 + rr + 8 * i) * R + r0 + cc] = __float2half_rn(s[cc][rr + 8 * i]);
}

// ---------------------------------------------------------------------------
// FFN1: h = silu(X W1) * (X W3). 3-stage cp.async pipeline, ldmatrix, fp16 HMMA.
__global__ __launch_bounds__(256, 2) void ffn1_kernel() {
    extern __shared__ __half smem_h[];

    const int NBT = FF / BN1;  // 64
    int bid = blockIdx.x;
    int tm = (bid / (GROUP * NBT)) * GROUP + (bid % GROUP);
    int nb = (bid % (GROUP * NBT)) / GROUP;
    if (tm >= MT) return;
    const int r0 = tm * BM;
    if (r0 >= g_offs[NE]) return;
    const int n0 = nb * BN1;

    int e = NE - 1;
#pragma unroll
    for (int i = 0; i < NE; i++)
        if (r0 >= g_offs[i] && r0 < g_offs[i + 1]) e = i;
    const __half* W1 = g_w1t + (size_t)e * FF * DD;
    const __half* W3 = g_w3t + (size_t)e * FF * DD;

    const int tid = threadIdx.x;
    const int lane = tid & 31, warp = tid >> 5;
    const int wm = (warp >> 1) * 32, wn = (warp & 1) * 32;
    const int grp = lane >> 2, qid = lane & 3;

    const int lrA = (lane & 7) + ((lane >> 3) & 1) * 8;
    const int kgA = (lane >> 4) * 8;
    const int lrB = (lane & 7) + ((lane >> 4) & 1) * 8;
    const int kgB = ((lane >> 3) & 1) * 8;

    uint32_t sm_u = (uint32_t)__cvta_generic_to_shared(smem_h);

    float acc1[2][4][4], acc3[2][4][4];
#pragma unroll
    for (int mi = 0; mi < 2; mi++)
#pragma unroll
        for (int ni = 0; ni < 4; ni++)
#pragma unroll
            for (int t = 0; t < 4; t++) { acc1[mi][ni][t] = 0.f; acc3[mi][ni][t] = 0.f; }

    const int NK = DD / BK;  // 16

    auto load_stage = [&](int slot, int k0) {
        uint32_t base = sm_u + slot * STG_H * 2;
#pragma unroll
        for (int i = 0; i < 4; i++) {
            int idx = tid + i * 256;
            int row = idx >> 3, c16 = (idx & 7) * 8;
            cp16(base + (row * PITCH + c16) * 2,
                 g_xh + (size_t)(r0 + row) * DD + k0 + c16);
        }
#pragma unroll
        for (int i = 0; i < 4; i++) {
            int idx = tid + i * 256;
            int mat = idx >> 9, row = (idx >> 3) & 63, c16 = (idx & 7) * 8;
            const __half* W = mat ? W3 : W1;
            cp16(base + (STA_H + (mat * 64 + row) * PITCH + c16) * 2,
                 W + (size_t)(n0 + row) * DD + k0 + c16);
        }
        CP_COMMIT();
    };

    load_stage(0, 0);
    load_stage(1, BK);

    for (int k = 0; k < NK; k++) {
        if (k + 1 < NK) CP_WAIT1(); else CP_WAIT0();
        __syncthreads();
        if (k + 2 < NK) load_stage((k + 2) % NSTAGE, (k + 2) * BK);

        int slot = k % NSTAGE;
        uint32_t Au = sm_u + slot * STG_H * 2;
        uint32_t Bu = Au + STA_H * 2;
#pragma unroll
        for (int c = 0; c < 4; c++) {
            int kc = c * 16;
            uint32_t a[2][4];
#pragma unroll
            for (int mi = 0; mi < 2; mi++)
                ldsm4(a[mi], Au + ((wm + mi * 16 + lrA) * PITCH + kc + kgA) * 2);
#pragma unroll
            for (int mat = 0; mat < 2; mat++) {
#pragma unroll
                for (int p = 0; p < 2; p++) {
                    uint32_t b[4];
                    ldsm4(b, Bu + ((mat * 64 + wn + p * 16 + lrB) * PITCH + kc + kgB) * 2);
#pragma unroll
                    for (int mi = 0; mi < 2; mi++) {
                        float* d0 = mat ? acc3[mi][p * 2 + 0] : acc1[mi][p * 2 + 0];
                        float* d1 = mat ? acc3[mi][p * 2 + 1] : acc1[mi][p * 2 + 1];
                        mma_f16(d0, a[mi], b[0], b[1]);
                        mma_f16(d1, a[mi], b[2], b[3]);
                    }
                }
            }
        }
    }

    // Epilogue: fast-math SwiGLU -> g_h (fp16)
#pragma unroll
    for (int mi = 0; mi < 2; mi++)
#pragma unroll
        for (int ni = 0; ni < 4; ni++)
#pragma unroll
            for (int t2 = 0; t2 < 2; t2++) {
                int row = r0 + wm + mi * 16 + grp + t2 * 8;
                int col = n0 + wn + ni * 8 + qid * 2;
                float s0 = swiglu(acc1[mi][ni][t2 * 2 + 0], acc3[mi][ni][t2 * 2 + 0]);
                float s1 = swiglu(acc1[mi][ni][t2 * 2 + 1], acc3[mi][ni][t2 * 2 + 1]);
                *reinterpret_cast<__half2*>(g_h + (size_t)row * FF + col) =
                    __floats2half2_rn(s0, s1);
            }
}

// ---------------------------------------------------------------------------
// FFN2: g_o[row] = h[row] @ W2. 3-stage pipeline.
__global__ __launch_bounds__(256, 2) void ffn2_kernel() {
    extern __shared__ __half smem_h[];

    const int NBT = DD / BN2;  // 8
    int bid = blockIdx.x;
    int tm = (bid / (GROUP * NBT)) * GROUP + (bid % GROUP);
    int nb = (bid % (GROUP * NBT)) / GROUP;
    if (tm >= MT) return;
    const int r0 = tm * BM;
    if (r0 >= g_offs[NE]) return;
    const int n0 = nb * BN2;

    int e = NE - 1;
#pragma unroll
    for (int i = 0; i < NE; i++)
        if (r0 >= g_offs[i] && r0 < g_offs[i + 1]) e = i;
    const __half* W2 = g_w2t + (size_t)e * DD * FF;

    const int tid = threadIdx.x;
    const int lane = tid & 31, warp = tid >> 5;
    const int wm = (warp >> 1) * 32, wn = (warp & 1) * 64;
    const int grp = lane >> 2, qid = lane & 3;

    const int lrA = (lane & 7) + ((lane >> 3) & 1) * 8;
    const int kgA = (lane >> 4) * 8;
    const int lrB = (lane & 7) + ((lane >> 4) & 1) * 8;
    const int kgB = ((lane >> 3) & 1) * 8;

    uint32_t sm_u = (uint32_t)__cvta_generic_to_shared(smem_h);

    float acc[2][8][4];
#pragma unroll
    for (int mi = 0; mi < 2; mi++)
#pragma unroll
        for (int ni = 0; ni < 8; ni++)
#pragma unroll
            for (int t = 0; t < 4; t++) acc[mi][ni][t] = 0.f;

    const int NK = FF / BK;  // 64

    auto load_stage = [&](int slot, int k0) {
        uint32_t base = sm_u + slot * STG_H * 2;
#pragma unroll
        for (int i = 0; i < 4; i++) {
            int idx = tid + i * 256;
            int row = idx >> 3, c16 = (idx & 7) * 8;
            cp16(base + (row * PITCH + c16) * 2,
                 g_h + (size_t)(r0 + row) * FF + k0 + c16);
        }
#pragma unroll
        for (int i = 0; i < 4; i++) {
            int idx = tid + i * 256;
            int row = idx >> 3, c16 = (idx & 7) * 8;
            cp16(base + (STA_H + row * PITCH + c16) * 2,
                 W2 + (size_t)(n0 + row) * FF + k0 + c16);
        }
        CP_COMMIT();
    };

    load_stage(0, 0);
    load_stage(1, BK);

    for (int k = 0; k < NK; k++) {
        if (k + 1 < NK) CP_WAIT1(); else CP_WAIT0();
        __syncthreads();
        if (k + 2 < NK) load_stage((k + 2) % NSTAGE, (k + 2) * BK);

        int slot = k % NSTAGE;
        uint32_t Au = sm_u + slot * STG_H * 2;
        uint32_t Bu = Au + STA_H * 2;
#pragma unroll
        for (int c = 0; c < 4; c++) {
            int kc = c * 16;
            uint32_t a[2][4];
#pragma unroll
            for (int mi = 0; mi < 2; mi++)
                ldsm4(a[mi], Au + ((wm + mi * 16 + lrA) * PITCH + kc + kgA) * 2);
#pragma unroll
            for (int p = 0; p < 4; p++) {
                uint32_t b[4];
                ldsm4(b, Bu + ((wn + p * 16 + lrB) * PITCH + kc + kgB) * 2);
#pragma unroll
                for (int mi = 0; mi < 2; mi++) {
                    mma_f16(acc[mi][p * 2 + 0], a[mi], b[0], b[1]);
                    mma_f16(acc[mi][p * 2 + 1], a[mi], b[2], b[3]);
                }
            }
        }
    }

#pragma unroll
    for (int mi = 0; mi < 2; mi++) {
#pragma unroll
        for (int t2 = 0; t2 < 2; t2++) {
            int row = r0 + wm + mi * 16 + grp + t2 * 8;
            float* op = g_o + (size_t)row * DD + n0;
#pragma unroll
            for (int ni = 0; ni < 8; ni++) {
                float2 v = make_float2(acc[mi][ni][t2 * 2 + 0], acc[mi][ni][t2 * 2 + 1]);
                *reinterpret_cast<float2*>(op + wn + ni * 8 + qid * 2) = v;
            }
        }
    }
}

// ---------------------------------------------------------------------------
__global__ void combine_kernel(float* __restrict__ out) {
    const int NC4 = DD / 4;
    int idx = blockIdx.x * blockDim.x + threadIdx.x;
    int stride = gridDim.x * blockDim.x;
    for (int i = idx; i < NT * NC4; i += stride) {
        int t = i / NC4, c = i % NC4;
        int p0 = g_tpos[2 * t + 0], p1 = g_tpos[2 * t + 1];
        float w0 = g_wt[p0], w1 = g_wt[p1];
        float4 v0 = reinterpret_cast<const float4*>(g_o)[(size_t)p0 * NC4 + c];
        float4 v1 = reinterpret_cast<const float4*>(g_o)[(size_t)p1 * NC4 + c];
        float4 r;
        r.x = w0 * v0.x + w1 * v1.x;
        r.y = w0 * v0.y + w1 * v1.y;
        r.z = w0 * v0.z + w1 * v1.z;
        r.w = w0 * v0.w + w1 * v1.w;
        reinterpret_cast<float4*>(out)[i] = r;
    }
}

// ---------------------------------------------------------------------------
extern "C" void kernel_launch(void* const* d_in, const int* in_sizes, int n_in,
                              void* d_out, int out_size) {
    const float* x  = (const float*)d_in[0];
    const float* gw = (const float*)d_in[1];
    const float* w1 = (const float*)d_in[2];
    const float* w3 = (const float*)d_in[3];
    const float* w2 = (const float*)d_in[4];
    float* out = (float*)d_out;

    static cudaStream_t s_aux = nullptr;
    static cudaEvent_t ev_fork = nullptr, ev_w13 = nullptr, ev_w2 = nullptr;
    if (s_aux == nullptr) {
        cudaStreamCreateWithFlags(&s_aux, cudaStreamNonBlocking);
        cudaEventCreateWithFlags(&ev_fork, cudaEventDisableTiming);
        cudaEventCreateWithFlags(&ev_w13, cudaEventDisableTiming);
        cudaEventCreateWithFlags(&ev_w2, cudaEventDisableTiming);
        cudaFuncSetAttribute(ffn1_kernel, cudaFuncAttributeMaxDynamicSharedMemorySize, SMEM_BYTES);
        cudaFuncSetAttribute(ffn2_kernel, cudaFuncAttributeMaxDynamicSharedMemorySize, SMEM_BYTES);
    }

    cudaEventRecord(ev_fork, 0);
    cudaStreamWaitEvent(s_aux, ev_fork, 0);

    transpose_w13_kernel<<<dim3(4096, 16), 256, 0, s_aux>>>(w1, w3);
    cudaEventRecord(ev_w13, s_aux);
    transpose_w2_kernel<<<dim3(4096, 8), 256, 0, s_aux>>>(w2);
    cudaEventRecord(ev_w2, s_aux);

    init_kernel<<<256, 256>>>();
    transpose_gw_kernel<<<32, 256>>>(gw);
    router_kernel<<<NT / 8, 256>>>(x);
    offsets_kernel<<<1, 1>>>();
    scatter_kernel<<<(NT + 255) / 256, 256>>>();
    gather_half_kernel<<<4096, 256>>>(x);

    cudaStreamWaitEvent(0, ev_w13, 0);
    ffn1_kernel<<<MTP * (FF / BN1), 256, SMEM_BYTES>>>();
    cudaStreamWaitEvent(0, ev_w2, 0);
    ffn2_kernel<<<MTP * (DD / BN2), 256, SMEM_BYTES>>>();
    combine_kernel<<<2048, 256>>>(out);
}

// round 16
// speedup vs baseline: 1.0897x; 1.0177x over previous
#include <cuda_runtime.h>
#include <cuda_fp16.h>
#include <cstdint>
#include <math.h>

#define NT 8192
#define DD 1024
#define FF 4096
#define NE 8
#define BM 128
#define BK 64
#define BN1 64
#define BN2 128
#define MAX_ROWS (NT*2 + NE*BM)   // 17408
#define MT (MAX_ROWS/BM)          // 136
#define GROUP 16
#define MTP (((MT+GROUP-1)/GROUP)*GROUP)   // 144

#define PITCH 72                     // halves per smem row (144B)
#define STA_H (BM*PITCH)             // 9216 halves
#define STB_H (128*PITCH)            // 9216 halves
#define STG_H (STA_H + STB_H)        // 18432 halves per stage
#define NSTAGE 3
#define SMEM_BYTES (NSTAGE * STG_H * 2)   // 110592

__device__ __align__(128) __half g_h[(size_t)MAX_ROWS * FF];
__device__ __align__(128) __half g_xh[(size_t)MAX_ROWS * DD];
__device__ __align__(128) __half g_w1t[(size_t)NE * FF * DD];
__device__ __align__(128) __half g_w3t[(size_t)NE * FF * DD];
__device__ __align__(128) __half g_w2t[(size_t)NE * DD * FF];
__device__ __align__(128) __half g_oh[(size_t)MAX_ROWS * DD];   // weighted ffn2 out (fp16)
__device__ __align__(128) float  g_gwt[NE * DD];
__device__ int   g_perm[MAX_ROWS];
__device__ float g_wt[MAX_ROWS];
__device__ int   g_tpos[NT * 2];
__device__ int   g_counts[NE];
__device__ int   g_offs[NE + 1];
__device__ int   g_cursor[NE];
__device__ int   g_eid[NT * 2];
__device__ float g_wr[NT * 2];

__device__ __forceinline__ void mma_f16(float c[4], const uint32_t a[4], const uint32_t b0, const uint32_t b1) {
    asm volatile(
        "mma.sync.aligned.m16n8k16.row.col.f32.f16.f16.f32 "
        "{%0,%1,%2,%3}, {%4,%5,%6,%7}, {%8,%9}, {%0,%1,%2,%3};\n"
        : "+f"(c[0]), "+f"(c[1]), "+f"(c[2]), "+f"(c[3])
        : "r"(a[0]), "r"(a[1]), "r"(a[2]), "r"(a[3]), "r"(b0), "r"(b1));
}
__device__ __forceinline__ void ldsm4(uint32_t r[4], uint32_t addr) {
    asm volatile("ldmatrix.sync.aligned.m8n8.x4.shared.b16 {%0,%1,%2,%3}, [%4];"
                 : "=r"(r[0]), "=r"(r[1]), "=r"(r[2]), "=r"(r[3]) : "r"(addr));
}
__device__ __forceinline__ void cp16(uint32_t dst, const void* src) {
    asm volatile("cp.async.cg.shared.global [%0], [%1], 16;\n" :: "r"(dst), "l"(src));
}
#define CP_COMMIT() asm volatile("cp.async.commit_group;\n")
#define CP_WAIT1()  asm volatile("cp.async.wait_group 1;\n")
#define CP_WAIT0()  asm volatile("cp.async.wait_group 0;\n")

__device__ __forceinline__ float swiglu(float a, float g) {
    return __fdividef(a, 1.f + __expf(-a)) * g;
}

// ---------------------------------------------------------------------------
__global__ void init_kernel() {
    int idx = blockIdx.x * blockDim.x + threadIdx.x;
    int stride = gridDim.x * blockDim.x;
    for (int i = idx; i < MAX_ROWS; i += stride) g_perm[i] = -1;
    if (idx < NE) g_counts[idx] = 0;
}

__global__ void transpose_gw_kernel(const float* __restrict__ gw) {
    int idx = blockIdx.x * blockDim.x + threadIdx.x;
    if (idx >= NE * DD) return;
    int d = idx >> 3, e = idx & 7;
    g_gwt[e * DD + d] = gw[idx];
}

__global__ void router_kernel(const float* __restrict__ x) {
    int warp = (blockIdx.x * blockDim.x + threadIdx.x) >> 5;
    int lane = threadIdx.x & 31;
    if (warp >= NT) return;
    const float4* xr = reinterpret_cast<const float4*>(x + (size_t)warp * DD);
    float4 xv[8];
#pragma unroll
    for (int i = 0; i < 8; i++) xv[i] = xr[i * 32 + lane];

    float acc[NE];
#pragma unroll
    for (int e = 0; e < NE; e++) {
        const float4* gr = reinterpret_cast<const float4*>(g_gwt + e * DD);
        float s = 0.f;
#pragma unroll
        for (int i = 0; i < 8; i++) {
            float4 g = gr[i * 32 + lane];
            s += xv[i].x * g.x + xv[i].y * g.y + xv[i].z * g.z + xv[i].w * g.w;
        }
        acc[e] = s;
    }
#pragma unroll
    for (int e = 0; e < NE; e++)
#pragma unroll
        for (int o = 16; o > 0; o >>= 1)
            acc[e] += __shfl_xor_sync(0xFFFFFFFFu, acc[e], o);
    if (lane == 0) {
        int i0 = 0; float v0 = acc[0];
#pragma unroll
        for (int e = 1; e < NE; e++) if (acc[e] > v0) { v0 = acc[e]; i0 = e; }
        int i1 = -1; float v1 = -1e30f;
#pragma unroll
        for (int e = 0; e < NE; e++) {
            if (e == i0) continue;
            if (acc[e] > v1) { v1 = acc[e]; i1 = e; }
        }
        float e1 = expf(v1 - v0);
        float inv = 1.f / (1.f + e1);
        g_eid[2 * warp + 0] = i0; g_wr[2 * warp + 0] = inv;
        g_eid[2 * warp + 1] = i1; g_wr[2 * warp + 1] = e1 * inv;
        atomicAdd(&g_counts[i0], 1);
        atomicAdd(&g_counts[i1], 1);
    }
}

__global__ void offsets_kernel() {
    int acc = 0;
    for (int e = 0; e < NE; e++) {
        g_offs[e] = acc; g_cursor[e] = acc;
        acc += (g_counts[e] + BM - 1) / BM * BM;
    }
    g_offs[NE] = acc;
}

__global__ void scatter_kernel() {
    int t = blockIdx.x * blockDim.x + threadIdx.x;
    if (t >= NT) return;
#pragma unroll
    for (int k = 0; k < 2; k++) {
        int e = g_eid[2 * t + k];
        int pos = atomicAdd(&g_cursor[e], 1);
        g_perm[pos] = t;
        g_wt[pos] = g_wr[2 * t + k];
        g_tpos[2 * t + k] = pos;
    }
}

__global__ void gather_half_kernel(const float* __restrict__ x) {
    const int NC8 = DD / 8;
    int idx = blockIdx.x * blockDim.x + threadIdx.x;
    int stride = gridDim.x * blockDim.x;
    for (int i = idx; i < MAX_ROWS * NC8; i += stride) {
        int r = i / NC8, c8 = i % NC8;
        int p = g_perm[r];
        union { uint4 u; __half2 h[4]; } pk;
        if (p >= 0) {
            const float4* xs = reinterpret_cast<const float4*>(x + (size_t)p * DD + c8 * 8);
            float4 v0 = xs[0], v1 = xs[1];
            pk.h[0] = __floats2half2_rn(v0.x, v0.y);
            pk.h[1] = __floats2half2_rn(v0.z, v0.w);
            pk.h[2] = __floats2half2_rn(v1.x, v1.y);
            pk.h[3] = __floats2half2_rn(v1.z, v1.w);
        } else {
            pk.u = make_uint4(0, 0, 0, 0);
        }
        reinterpret_cast<uint4*>(g_xh)[(size_t)r * NC8 + c8] = pk.u;
    }
}

// Fast transpose: 64x32 tiles, half2 stores (128B/warp store transactions).
__global__ void transpose_w13_kernel(const float* __restrict__ w1,
                                     const float* __restrict__ w3) {
    __shared__ float s[64][33];
    int z = blockIdx.y, m = z >> 3, e = z & 7;
    const float* src = (m ? w3 : w1) + (size_t)e * DD * FF;
    __half* dst = (m ? g_w3t : g_w1t) + (size_t)e * FF * DD;
    const int tpc = FF / 32;   // 128
    int r0 = (blockIdx.x / tpc) * 64, c0 = (blockIdx.x % tpc) * 32;
    int tid = threadIdx.x;
#pragma unroll
    for (int i = 0; i < 8; i++) {
        int idx = tid + i * 256;
        int row = idx >> 5, col = idx & 31;
        s[row][col] = src[(size_t)(r0 + row) * FF + c0 + col];
    }
    __syncthreads();
#pragma unroll
    for (int i = 0; i < 4; i++) {
        int idx = tid + i * 256;
        int cr = idx >> 5, h2 = idx & 31;
        int dc = h2 * 2;
        __half2 v = __floats2half2_rn(s[dc][cr], s[dc + 1][cr]);
        *reinterpret_cast<__half2*>(dst + (size_t)(c0 + cr) * DD + r0 + dc) = v;
    }
}

__global__ void transpose_w2_kernel(const float* __restrict__ w2) {
    __shared__ float s[64][33];
    int e = blockIdx.y;
    const float* src = w2 + (size_t)e * FF * DD;
    __half* dst = g_w2t + (size_t)e * DD * FF;
    const int tpc = DD / 32;   // 32
    int r0 = (blockIdx.x / tpc) * 64, c0 = (blockIdx.x % tpc) * 32;
    int tid = threadIdx.x;
#pragma unroll
    for (int i = 0; i < 8; i++) {
        int idx = tid + i * 256;
        int row = idx >> 5, col = idx & 31;
        s[row][col] = src[(size_t)(r0 + row) * DD + c0 + col];
    }
    __syncthreads();
#pragma unroll
    for (int i = 0; i < 4; i++) {
        int idx = tid + i * 256;
        int cr = idx >> 5, h2 = idx & 31;
        int dc = h2 * 2;
        __half2 v = __floats2half2_rn(s[dc][cr], s[dc + 1][cr]);
        *reinterpret_cast<__half2*>(dst + (size_t)(c0 + cr) * FF + r0 + dc) = v;
    }
}

// ---------------------------------------------------------------------------
// FFN1: h = silu(X W1) * (X W3). 3-stage cp.async pipeline, ldmatrix, fp16 HMMA.
__global__ __launch_bounds__(256, 2) void ffn1_kernel() {
    extern __shared__ __half smem_h[];

    const int NBT = FF / BN1;  // 64
    int bid = blockIdx.x;
    int tm = (bid / (GROUP * NBT)) * GROUP + (bid % GROUP);
    int nb = (bid % (GROUP * NBT)) / GROUP;
    if (tm >= MT) return;
    const int r0 = tm * BM;
    if (r0 >= g_offs[NE]) return;
    const int n0 = nb * BN1;

    int e = NE - 1;
#pragma unroll
    for (int i = 0; i < NE; i++)
        if (r0 >= g_offs[i] && r0 < g_offs[i + 1]) e = i;
    const __half* W1 = g_w1t + (size_t)e * FF * DD;
    const __half* W3 = g_w3t + (size_t)e * FF * DD;

    const int tid = threadIdx.x;
    const int lane = tid & 31, warp = tid >> 5;
    const int wm = (warp >> 1) * 32, wn = (warp & 1) * 32;
    const int grp = lane >> 2, qid = lane & 3;

    const int lrA = (lane & 7) + ((lane >> 3) & 1) * 8;
    const int kgA = (lane >> 4) * 8;
    const int lrB = (lane & 7) + ((lane >> 4) & 1) * 8;
    const int kgB = ((lane >> 3) & 1) * 8;

    uint32_t sm_u = (uint32_t)__cvta_generic_to_shared(smem_h);

    float acc1[2][4][4], acc3[2][4][4];
#pragma unroll
    for (int mi = 0; mi < 2; mi++)
#pragma unroll
        for (int ni = 0; ni < 4; ni++)
#pragma unroll
            for (int t = 0; t < 4; t++) { acc1[mi][ni][t] = 0.f; acc3[mi][ni][t] = 0.f; }

    const int NK = DD / BK;  // 16

    auto load_stage = [&](int slot, int k0) {
        uint32_t base = sm_u + slot * STG_H * 2;
#pragma unroll
        for (int i = 0; i < 4; i++) {
            int idx = tid + i * 256;
            int row = idx >> 3, c16 = (idx & 7) * 8;
            cp16(base + (row * PITCH + c16) * 2,
                 g_xh + (size_t)(r0 + row) * DD + k0 + c16);
        }
#pragma unroll
        for (int i = 0; i < 4; i++) {
            int idx = tid + i * 256;
            int mat = idx >> 9, row = (idx >> 3) & 63, c16 = (idx & 7) * 8;
            const __half* W = mat ? W3 : W1;
            cp16(base + (STA_H + (mat * 64 + row) * PITCH + c16) * 2,
                 W + (size_t)(n0 + row) * DD + k0 + c16);
        }
        CP_COMMIT();
    };

    load_stage(0, 0);
    load_stage(1, BK);

    for (int k = 0; k < NK; k++) {
        if (k + 1 < NK) CP_WAIT1(); else CP_WAIT0();
        __syncthreads();
        if (k + 2 < NK) load_stage((k + 2) % NSTAGE, (k + 2) * BK);

        int slot = k % NSTAGE;
        uint32_t Au = sm_u + slot * STG_H * 2;
        uint32_t Bu = Au + STA_H * 2;
#pragma unroll
        for (int c = 0; c < 4; c++) {
            int kc = c * 16;
            uint32_t a[2][4];
#pragma unroll
            for (int mi = 0; mi < 2; mi++)
                ldsm4(a[mi], Au + ((wm + mi * 16 + lrA) * PITCH + kc + kgA) * 2);
#pragma unroll
            for (int mat = 0; mat < 2; mat++) {
#pragma unroll
                for (int p = 0; p < 2; p++) {
                    uint32_t b[4];
                    ldsm4(b, Bu + ((mat * 64 + wn + p * 16 + lrB) * PITCH + kc + kgB) * 2);
#pragma unroll
                    for (int mi = 0; mi < 2; mi++) {
                        float* d0 = mat ? acc3[mi][p * 2 + 0] : acc1[mi][p * 2 + 0];
                        float* d1 = mat ? acc3[mi][p * 2 + 1] : acc1[mi][p * 2 + 1];
                        mma_f16(d0, a[mi], b[0], b[1]);
                        mma_f16(d1, a[mi], b[2], b[3]);
                    }
                }
            }
        }
    }

#pragma unroll
    for (int mi = 0; mi < 2; mi++)
#pragma unroll
        for (int ni = 0; ni < 4; ni++)
#pragma unroll
            for (int t2 = 0; t2 < 2; t2++) {
                int row = r0 + wm + mi * 16 + grp + t2 * 8;
                int col = n0 + wn + ni * 8 + qid * 2;
                float s0 = swiglu(acc1[mi][ni][t2 * 2 + 0], acc3[mi][ni][t2 * 2 + 0]);
                float s1 = swiglu(acc1[mi][ni][t2 * 2 + 1], acc3[mi][ni][t2 * 2 + 1]);
                *reinterpret_cast<__half2*>(g_h + (size_t)row * FF + col) =
                    __floats2half2_rn(s0, s1);
            }
}

// ---------------------------------------------------------------------------
// FFN2: g_oh[row] = wt[row] * (h[row] @ W2), fp16 store. 3-stage pipeline.
__global__ __launch_bounds__(256, 2) void ffn2_kernel() {
    extern __shared__ __half smem_h[];

    const int NBT = DD / BN2;  // 8
    int bid = blockIdx.x;
    int tm = (bid / (GROUP * NBT)) * GROUP + (bid % GROUP);
    int nb = (bid % (GROUP * NBT)) / GROUP;
    if (tm >= MT) return;
    const int r0 = tm * BM;
    if (r0 >= g_offs[NE]) return;
    const int n0 = nb * BN2;

    int e = NE - 1;
#pragma unroll
    for (int i = 0; i < NE; i++)
        if (r0 >= g_offs[i] && r0 < g_offs[i + 1]) e = i;
    const __half* W2 = g_w2t + (size_t)e * DD * FF;

    const int tid = threadIdx.x;
    const int lane = tid & 31, warp = tid >> 5;
    const int wm = (warp >> 1) * 32, wn = (warp & 1) * 64;
    const int grp = lane >> 2, qid = lane & 3;

    const int lrA = (lane & 7) + ((lane >> 3) & 1) * 8;
    const int kgA = (lane >> 4) * 8;
    const int lrB = (lane & 7) + ((lane >> 4) & 1) * 8;
    const int kgB = ((lane >> 3) & 1) * 8;

    uint32_t sm_u = (uint32_t)__cvta_generic_to_shared(smem_h);

    float acc[2][8][4];
#pragma unroll
    for (int mi = 0; mi < 2; mi++)
#pragma unroll
        for (int ni = 0; ni < 8; ni++)
#pragma unroll
            for (int t = 0; t < 4; t++) acc[mi][ni][t] = 0.f;

    const int NK = FF / BK;  // 64

    auto load_stage = [&](int slot, int k0) {
        uint32_t base = sm_u + slot * STG_H * 2;
#pragma unroll
        for (int i = 0; i < 4; i++) {
            int idx = tid + i * 256;
            int row = idx >> 3, c16 = (idx & 7) * 8;
            cp16(base + (row * PITCH + c16) * 2,
                 g_h + (size_t)(r0 + row) * FF + k0 + c16);
        }
#pragma unroll
        for (int i = 0; i < 4; i++) {
            int idx = tid + i * 256;
            int row = idx >> 3, c16 = (idx & 7) * 8;
            cp16(base + (STA_H + row * PITCH + c16) * 2,
                 W2 + (size_t)(n0 + row) * FF + k0 + c16);
        }
        CP_COMMIT();
    };

    load_stage(0, 0);
    load_stage(1, BK);

    for (int k = 0; k < NK; k++) {
        if (k + 1 < NK) CP_WAIT1(); else CP_WAIT0();
        __syncthreads();
        if (k + 2 < NK) load_stage((k + 2) % NSTAGE, (k + 2) * BK);

        int slot = k % NSTAGE;
        uint32_t Au = sm_u + slot * STG_H * 2;
        uint32_t Bu = Au + STA_H * 2;
#pragma unroll
        for (int c = 0; c < 4; c++) {
            int kc = c * 16;
            uint32_t a[2][4];
#pragma unroll
            for (int mi = 0; mi < 2; mi++)
                ldsm4(a[mi], Au + ((wm + mi * 16 + lrA) * PITCH + kc + kgA) * 2);
#pragma unroll
            for (int p = 0; p < 4; p++) {
                uint32_t b[4];
                ldsm4(b, Bu + ((wn + p * 16 + lrB) * PITCH + kc + kgB) * 2);
#pragma unroll
                for (int mi = 0; mi < 2; mi++) {
                    mma_f16(acc[mi][p * 2 + 0], a[mi], b[0], b[1]);
                    mma_f16(acc[mi][p * 2 + 1], a[mi], b[2], b[3]);
                }
            }
        }
    }

    // Epilogue: apply routing weight (fp32), store fp16
#pragma unroll
    for (int mi = 0; mi < 2; mi++) {
#pragma unroll
        for (int t2 = 0; t2 < 2; t2++) {
            int row = r0 + wm + mi * 16 + grp + t2 * 8;
            float w = g_wt[row];
            __half* op = g_oh + (size_t)row * DD + n0;
#pragma unroll
            for (int ni = 0; ni < 8; ni++) {
                __half2 v = __floats2half2_rn(acc[mi][ni][t2 * 2 + 0] * w,
                                              acc[mi][ni][t2 * 2 + 1] * w);
                *reinterpret_cast<__half2*>(op + wn + ni * 8 + qid * 2) = v;
            }
        }
    }
}

// ---------------------------------------------------------------------------
// Combine: out[t] = oh[pos0] + oh[pos1]   (weights already applied in ffn2)
__global__ void combine_kernel(float* __restrict__ out) {
    const int NC8 = DD / 8;
    int idx = blockIdx.x * blockDim.x + threadIdx.x;
    int stride = gridDim.x * blockDim.x;
    for (int i = idx; i < NT * NC8; i += stride) {
        int t = i / NC8, c = i % NC8;
        int p0 = g_tpos[2 * t + 0], p1 = g_tpos[2 * t + 1];
        union { uint4 u; __half2 h[4]; } a, b;
        a.u = reinterpret_cast<const uint4*>(g_oh)[(size_t)p0 * NC8 + c];
        b.u = reinterpret_cast<const uint4*>(g_oh)[(size_t)p1 * NC8 + c];
        float4 r0, r1;
        float2 s;
        s = __half22float2(a.h[0]); float2 q = __half22float2(b.h[0]);
        r0.x = s.x + q.x; r0.y = s.y + q.y;
        s = __half22float2(a.h[1]); q = __half22float2(b.h[1]);
        r0.z = s.x + q.x; r0.w = s.y + q.y;
        s = __half22float2(a.h[2]); q = __half22float2(b.h[2]);
        r1.x = s.x + q.x; r1.y = s.y + q.y;
        s = __half22float2(a.h[3]); q = __half22float2(b.h[3]);
        r1.z = s.x + q.x; r1.w = s.y + q.y;
        reinterpret_cast<float4*>(out)[(size_t)i * 2 + 0] = r0;
        reinterpret_cast<float4*>(out)[(size_t)i * 2 + 1] = r1;
    }
}

// ---------------------------------------------------------------------------
extern "C" void kernel_launch(void* const* d_in, const int* in_sizes, int n_in,
                              void* d_out, int out_size) {
    const float* x  = (const float*)d_in[0];
    const float* gw = (const float*)d_in[1];
    const float* w1 = (const float*)d_in[2];
    const float* w3 = (const float*)d_in[3];
    const float* w2 = (const float*)d_in[4];
    float* out = (float*)d_out;

    static cudaStream_t s_aux = nullptr;
    static cudaEvent_t ev_fork = nullptr, ev_w13 = nullptr, ev_w2 = nullptr;
    if (s_aux == nullptr) {
        cudaStreamCreateWithFlags(&s_aux, cudaStreamNonBlocking);
        cudaEventCreateWithFlags(&ev_fork, cudaEventDisableTiming);
        cudaEventCreateWithFlags(&ev_w13, cudaEventDisableTiming);
        cudaEventCreateWithFlags(&ev_w2, cudaEventDisableTiming);
        cudaFuncSetAttribute(ffn1_kernel, cudaFuncAttributeMaxDynamicSharedMemorySize, SMEM_BYTES);
        cudaFuncSetAttribute(ffn2_kernel, cudaFuncAttributeMaxDynamicSharedMemorySize, SMEM_BYTES);
    }

    cudaEventRecord(ev_fork, 0);
    cudaStreamWaitEvent(s_aux, ev_fork, 0);

    transpose_w13_kernel<<<dim3((DD / 64) * (FF / 32), 16), 256, 0, s_aux>>>(w1, w3);
    cudaEventRecord(ev_w13, s_aux);
    transpose_w2_kernel<<<dim3((FF / 64) * (DD / 32), 8), 256, 0, s_aux>>>(w2);
    cudaEventRecord(ev_w2, s_aux);

    init_kernel<<<256, 256>>>();
    transpose_gw_kernel<<<32, 256>>>(gw);
    router_kernel<<<NT / 8, 256>>>(x);
    offsets_kernel<<<1, 1>>>();
    scatter_kernel<<<(NT + 255) / 256, 256>>>();
    gather_half_kernel<<<4096, 256>>>(x);

    cudaStreamWaitEvent(0, ev_w13, 0);
    ffn1_kernel<<<MTP * (FF / BN1), 256, SMEM_BYTES>>>();
    cudaStreamWaitEvent(0, ev_w2, 0);
    ffn2_kernel<<<MTP * (DD / BN2), 256, SMEM_BYTES>>>();
    combine_kernel<<<2048, 256>>>(out);
}

// round 17
// speedup vs baseline: 1.0985x; 1.0081x over previous
#include <cuda_runtime.h>
#include <cuda_fp16.h>
#include <cstdint>
#include <math.h>

#define NT 8192
#define DD 1024
#define FF 4096
#define NE 8
#define BM 128
#define BK 64
#define BN1 64
#define BN2 128
#define MAX_ROWS (NT*2 + NE*BM)   // 17408
#define MT (MAX_ROWS/BM)          // 136
#define GROUP 16
#define MTP (((MT+GROUP-1)/GROUP)*GROUP)   // 144

#define PITCH 72                     // halves per smem row (144B)
#define STA_H (BM*PITCH)             // 9216 halves
#define STB_H (128*PITCH)            // 9216 halves
#define STG_H (STA_H + STB_H)        // 18432 halves per stage
#define NSTAGE 3
#define SMEM_BYTES (NSTAGE * STG_H * 2)   // 110592

__device__ __align__(128) __half g_h[(size_t)MAX_ROWS * FF];
__device__ __align__(128) __half g_xh[(size_t)NT * DD];        // dense fp16 copy of x
__device__ __align__(128) __half g_w1t[(size_t)NE * FF * DD];
__device__ __align__(128) __half g_w3t[(size_t)NE * FF * DD];
__device__ __align__(128) __half g_w2t[(size_t)NE * DD * FF];
__device__ __align__(128) __half g_oh[(size_t)MAX_ROWS * DD];  // weighted ffn2 out (fp16)
__device__ __align__(128) float  g_gwt[NE * DD];
__device__ int   g_perm[MAX_ROWS];
__device__ float g_wt[MAX_ROWS];
__device__ int   g_tpos[NT * 2];
__device__ int   g_counts[NE];
__device__ int   g_offs[NE + 1];
__device__ int   g_cursor[NE];
__device__ int   g_eid[NT * 2];
__device__ float g_wr[NT * 2];

__device__ __forceinline__ void mma_f16(float c[4], const uint32_t a[4], const uint32_t b0, const uint32_t b1) {
    asm volatile(
        "mma.sync.aligned.m16n8k16.row.col.f32.f16.f16.f32 "
        "{%0,%1,%2,%3}, {%4,%5,%6,%7}, {%8,%9}, {%0,%1,%2,%3};\n"
        : "+f"(c[0]), "+f"(c[1]), "+f"(c[2]), "+f"(c[3])
        : "r"(a[0]), "r"(a[1]), "r"(a[2]), "r"(a[3]), "r"(b0), "r"(b1));
}
__device__ __forceinline__ void ldsm4(uint32_t r[4], uint32_t addr) {
    asm volatile("ldmatrix.sync.aligned.m8n8.x4.shared.b16 {%0,%1,%2,%3}, [%4];"
                 : "=r"(r[0]), "=r"(r[1]), "=r"(r[2]), "=r"(r[3]) : "r"(addr));
}
__device__ __forceinline__ void cp16(uint32_t dst, const void* src) {
    asm volatile("cp.async.cg.shared.global [%0], [%1], 16;\n" :: "r"(dst), "l"(src));
}
// Predicated: pred==false copies 0 bytes and zero-fills the 16B destination.
__device__ __forceinline__ void cp16z(uint32_t dst, const void* src, bool pred) {
    int sz = pred ? 16 : 0;
    asm volatile("cp.async.cg.shared.global [%0], [%1], 16, %2;\n"
                 :: "r"(dst), "l"(src), "r"(sz));
}
#define CP_COMMIT() asm volatile("cp.async.commit_group;\n")
#define CP_WAIT1()  asm volatile("cp.async.wait_group 1;\n")
#define CP_WAIT0()  asm volatile("cp.async.wait_group 0;\n")

__device__ __forceinline__ float swiglu(float a, float g) {
    return __fdividef(a, 1.f + __expf(-a)) * g;
}

// ---------------------------------------------------------------------------
__global__ void init_kernel() {
    int idx = blockIdx.x * blockDim.x + threadIdx.x;
    int stride = gridDim.x * blockDim.x;
    for (int i = idx; i < MAX_ROWS; i += stride) g_perm[i] = -1;
    if (idx < NE) g_counts[idx] = 0;
}

__global__ void transpose_gw_kernel(const float* __restrict__ gw) {
    int idx = blockIdx.x * blockDim.x + threadIdx.x;
    if (idx >= NE * DD) return;
    int d = idx >> 3, e = idx & 7;
    g_gwt[e * DD + d] = gw[idx];
}

// Dense fp32 -> fp16 convert of x (token order). No router dependency.
__global__ void convert_x_kernel(const float* __restrict__ x) {
    int idx = blockIdx.x * blockDim.x + threadIdx.x;
    int stride = gridDim.x * blockDim.x;
    const int N8 = NT * DD / 8;
    for (int i = idx; i < N8; i += stride) {
        const float4* xs = reinterpret_cast<const float4*>(x + (size_t)i * 8);
        float4 v0 = xs[0], v1 = xs[1];
        union { uint4 u; __half2 h[4]; } pk;
        pk.h[0] = __floats2half2_rn(v0.x, v0.y);
        pk.h[1] = __floats2half2_rn(v0.z, v0.w);
        pk.h[2] = __floats2half2_rn(v1.x, v1.y);
        pk.h[3] = __floats2half2_rn(v1.z, v1.w);
        reinterpret_cast<uint4*>(g_xh)[i] = pk.u;
    }
}

__global__ void router_kernel(const float* __restrict__ x) {
    int warp = (blockIdx.x * blockDim.x + threadIdx.x) >> 5;
    int lane = threadIdx.x & 31;
    if (warp >= NT) return;
    const float4* xr = reinterpret_cast<const float4*>(x + (size_t)warp * DD);
    float4 xv[8];
#pragma unroll
    for (int i = 0; i < 8; i++) xv[i] = xr[i * 32 + lane];

    float acc[NE];
#pragma unroll
    for (int e = 0; e < NE; e++) {
        const float4* gr = reinterpret_cast<const float4*>(g_gwt + e * DD);
        float s = 0.f;
#pragma unroll
        for (int i = 0; i < 8; i++) {
            float4 g = gr[i * 32 + lane];
            s += xv[i].x * g.x + xv[i].y * g.y + xv[i].z * g.z + xv[i].w * g.w;
        }
        acc[e] = s;
    }
#pragma unroll
    for (int e = 0; e < NE; e++)
#pragma unroll
        for (int o = 16; o > 0; o >>= 1)
            acc[e] += __shfl_xor_sync(0xFFFFFFFFu, acc[e], o);
    if (lane == 0) {
        int i0 = 0; float v0 = acc[0];
#pragma unroll
        for (int e = 1; e < NE; e++) if (acc[e] > v0) { v0 = acc[e]; i0 = e; }
        int i1 = -1; float v1 = -1e30f;
#pragma unroll
        for (int e = 0; e < NE; e++) {
            if (e == i0) continue;
            if (acc[e] > v1) { v1 = acc[e]; i1 = e; }
        }
        float e1 = expf(v1 - v0);
        float inv = 1.f / (1.f + e1);
        g_eid[2 * warp + 0] = i0; g_wr[2 * warp + 0] = inv;
        g_eid[2 * warp + 1] = i1; g_wr[2 * warp + 1] = e1 * inv;
        atomicAdd(&g_counts[i0], 1);
        atomicAdd(&g_counts[i1], 1);
    }
}

__global__ void offsets_kernel() {
    int acc = 0;
    for (int e = 0; e < NE; e++) {
        g_offs[e] = acc; g_cursor[e] = acc;
        acc += (g_counts[e] + BM - 1) / BM * BM;
    }
    g_offs[NE] = acc;
}

__global__ void scatter_kernel() {
    int t = blockIdx.x * blockDim.x + threadIdx.x;
    if (t >= NT) return;
#pragma unroll
    for (int k = 0; k < 2; k++) {
        int e = g_eid[2 * t + k];
        int pos = atomicAdd(&g_cursor[e], 1);
        g_perm[pos] = t;
        g_wt[pos] = g_wr[2 * t + k];
        g_tpos[2 * t + k] = pos;
    }
}

// Fast transpose: 64x32 tiles, half2 stores.
__global__ void transpose_w13_kernel(const float* __restrict__ w1,
                                     const float* __restrict__ w3) {
    __shared__ float s[64][33];
    int z = blockIdx.y, m = z >> 3, e = z & 7;
    const float* src = (m ? w3 : w1) + (size_t)e * DD * FF;
    __half* dst = (m ? g_w3t : g_w1t) + (size_t)e * FF * DD;
    const int tpc = FF / 32;   // 128
    int r0 = (blockIdx.x / tpc) * 64, c0 = (blockIdx.x % tpc) * 32;
    int tid = threadIdx.x;
#pragma unroll
    for (int i = 0; i < 8; i++) {
        int idx = tid + i * 256;
        int row = idx >> 5, col = idx & 31;
        s[row][col] = src[(size_t)(r0 + row) * FF + c0 + col];
    }
    __syncthreads();
#pragma unroll
    for (int i = 0; i < 4; i++) {
        int idx = tid + i * 256;
        int cr = idx >> 5, h2 = idx & 31;
        int dc = h2 * 2;
        __half2 v = __floats2half2_rn(s[dc][cr], s[dc + 1][cr]);
        *reinterpret_cast<__half2*>(dst + (size_t)(c0 + cr) * DD + r0 + dc) = v;
    }
}

__global__ void transpose_w2_kernel(const float* __restrict__ w2) {
    __shared__ float s[64][33];
    int e = blockIdx.y;
    const float* src = w2 + (size_t)e * FF * DD;
    __half* dst = g_w2t + (size_t)e * DD * FF;
    const int tpc = DD / 32;   // 32
    int r0 = (blockIdx.x / tpc) * 64, c0 = (blockIdx.x % tpc) * 32;
    int tid = threadIdx.x;
#pragma unroll
    for (int i = 0; i < 8; i++) {
        int idx = tid + i * 256;
        int row = idx >> 5, col = idx & 31;
        s[row][col] = src[(size_t)(r0 + row) * DD + c0 + col];
    }
    __syncthreads();
#pragma unroll
    for (int i = 0; i < 4; i++) {
        int idx = tid + i * 256;
        int cr = idx >> 5, h2 = idx & 31;
        int dc = h2 * 2;
        __half2 v = __floats2half2_rn(s[dc][cr], s[dc + 1][cr]);
        *reinterpret_cast<__half2*>(dst + (size_t)(c0 + cr) * FF + r0 + dc) = v;
    }
}

// ---------------------------------------------------------------------------
// FFN1: h = silu(X W1) * (X W3). Gather fused into A-load via g_perm.
__global__ __launch_bounds__(256, 2) void ffn1_kernel() {
    extern __shared__ __half smem_h[];

    const int NBT = FF / BN1;  // 64
    int bid = blockIdx.x;
    int tm = (bid / (GROUP * NBT)) * GROUP + (bid % GROUP);
    int nb = (bid % (GROUP * NBT)) / GROUP;
    if (tm >= MT) return;
    const int r0 = tm * BM;
    if (r0 >= g_offs[NE]) return;
    const int n0 = nb * BN1;

    int e = NE - 1;
#pragma unroll
    for (int i = 0; i < NE; i++)
        if (r0 >= g_offs[i] && r0 < g_offs[i + 1]) e = i;
    const __half* W1 = g_w1t + (size_t)e * FF * DD;
    const __half* W3 = g_w3t + (size_t)e * FF * DD;

    const int tid = threadIdx.x;
    const int lane = tid & 31, warp = tid >> 5;
    const int wm = (warp >> 1) * 32, wn = (warp & 1) * 32;
    const int grp = lane >> 2, qid = lane & 3;

    const int lrA = (lane & 7) + ((lane >> 3) & 1) * 8;
    const int kgA = (lane >> 4) * 8;
    const int lrB = (lane & 7) + ((lane >> 4) & 1) * 8;
    const int kgB = ((lane >> 3) & 1) * 8;

    // perm cache for this thread's 4 A-load rows
    int pr[4];
#pragma unroll
    for (int i = 0; i < 4; i++) pr[i] = g_perm[r0 + (tid >> 3) + 32 * i];

    uint32_t sm_u = (uint32_t)__cvta_generic_to_shared(smem_h);

    float acc1[2][4][4], acc3[2][4][4];
#pragma unroll
    for (int mi = 0; mi < 2; mi++)
#pragma unroll
        for (int ni = 0; ni < 4; ni++)
#pragma unroll
            for (int t = 0; t < 4; t++) { acc1[mi][ni][t] = 0.f; acc3[mi][ni][t] = 0.f; }

    const int NK = DD / BK;  // 16

    auto load_stage = [&](int slot, int k0) {
        uint32_t base = sm_u + slot * STG_H * 2;
#pragma unroll
        for (int i = 0; i < 4; i++) {
            int row = (tid >> 3) + 32 * i;
            int c16 = (tid & 7) * 8;
            int p = pr[i];
            cp16z(base + (row * PITCH + c16) * 2,
                  g_xh + (size_t)(p < 0 ? 0 : p) * DD + k0 + c16, p >= 0);
        }
#pragma unroll
        for (int i = 0; i < 4; i++) {
            int idx = tid + i * 256;
            int mat = idx >> 9, row = (idx >> 3) & 63, c16 = (idx & 7) * 8;
            const __half* W = mat ? W3 : W1;
            cp16(base + (STA_H + (mat * 64 + row) * PITCH + c16) * 2,
                 W + (size_t)(n0 + row) * DD + k0 + c16);
        }
        CP_COMMIT();
    };

    load_stage(0, 0);
    load_stage(1, BK);

    for (int k = 0; k < NK; k++) {
        if (k + 1 < NK) CP_WAIT1(); else CP_WAIT0();
        __syncthreads();
        if (k + 2 < NK) load_stage((k + 2) % NSTAGE, (k + 2) * BK);

        int slot = k % NSTAGE;
        uint32_t Au = sm_u + slot * STG_H * 2;
        uint32_t Bu = Au + STA_H * 2;
#pragma unroll
        for (int c = 0; c < 4; c++) {
            int kc = c * 16;
            uint32_t a[2][4];
#pragma unroll
            for (int mi = 0; mi < 2; mi++)
                ldsm4(a[mi], Au + ((wm + mi * 16 + lrA) * PITCH + kc + kgA) * 2);
#pragma unroll
            for (int mat = 0; mat < 2; mat++) {
#pragma unroll
                for (int p = 0; p < 2; p++) {
                    uint32_t b[4];
                    ldsm4(b, Bu + ((mat * 64 + wn + p * 16 + lrB) * PITCH + kc + kgB) * 2);
#pragma unroll
                    for (int mi = 0; mi < 2; mi++) {
                        float* d0 = mat ? acc3[mi][p * 2 + 0] : acc1[mi][p * 2 + 0];
                        float* d1 = mat ? acc3[mi][p * 2 + 1] : acc1[mi][p * 2 + 1];
                        mma_f16(d0, a[mi], b[0], b[1]);
                        mma_f16(d1, a[mi], b[2], b[3]);
                    }
                }
            }
        }
    }

#pragma unroll
    for (int mi = 0; mi < 2; mi++)
#pragma unroll
        for (int ni = 0; ni < 4; ni++)
#pragma unroll
            for (int t2 = 0; t2 < 2; t2++) {
                int row = r0 + wm + mi * 16 + grp + t2 * 8;
                int col = n0 + wn + ni * 8 + qid * 2;
                float s0 = swiglu(acc1[mi][ni][t2 * 2 + 0], acc3[mi][ni][t2 * 2 + 0]);
                float s1 = swiglu(acc1[mi][ni][t2 * 2 + 1], acc3[mi][ni][t2 * 2 + 1]);
                *reinterpret_cast<__half2*>(g_h + (size_t)row * FF + col) =
                    __floats2half2_rn(s0, s1);
            }
}

// ---------------------------------------------------------------------------
// FFN2: g_oh[row] = wt[row] * (h[row] @ W2), fp16 store.
__global__ __launch_bounds__(256, 2) void ffn2_kernel() {
    extern __shared__ __half smem_h[];

    const int NBT = DD / BN2;  // 8
    int bid = blockIdx.x;
    int tm = (bid / (GROUP * NBT)) * GROUP + (bid % GROUP);
    int nb = (bid % (GROUP * NBT)) / GROUP;
    if (tm >= MT) return;
    const int r0 = tm * BM;
    if (r0 >= g_offs[NE]) return;
    const int n0 = nb * BN2;

    int e = NE - 1;
#pragma unroll
    for (int i = 0; i < NE; i++)
        if (r0 >= g_offs[i] && r0 < g_offs[i + 1]) e = i;
    const __half* W2 = g_w2t + (size_t)e * DD * FF;

    const int tid = threadIdx.x;
    const int lane = tid & 31, warp = tid >> 5;
    const int wm = (warp >> 1) * 32, wn = (warp & 1) * 64;
    const int grp = lane >> 2, qid = lane & 3;

    const int lrA = (lane & 7) + ((lane >> 3) & 1) * 8;
    const int kgA = (lane >> 4) * 8;
    const int lrB = (lane & 7) + ((lane >> 4) & 1) * 8;
    const int kgB = ((lane >> 3) & 1) * 8;

    uint32_t sm_u = (uint32_t)__cvta_generic_to_shared(smem_h);

    float acc[2][8][4];
#pragma unroll
    for (int mi = 0; mi < 2; mi++)
#pragma unroll
        for (int ni = 0; ni < 8; ni++)
#pragma unroll
            for (int t = 0; t < 4; t++) acc[mi][ni][t] = 0.f;

    const int NK = FF / BK;  // 64

    auto load_stage = [&](int slot, int k0) {
        uint32_t base = sm_u + slot * STG_H * 2;
#pragma unroll
        for (int i = 0; i < 4; i++) {
            int idx = tid + i * 256;
            int row = idx >> 3, c16 = (idx & 7) * 8;
            cp16(base + (row * PITCH + c16) * 2,
                 g_h + (size_t)(r0 + row) * FF + k0 + c16);
        }
#pragma unroll
        for (int i = 0; i < 4; i++) {
            int idx = tid + i * 256;
            int row = idx >> 3, c16 = (idx & 7) * 8;
            cp16(base + (STA_H + row * PITCH + c16) * 2,
                 W2 + (size_t)(n0 + row) * FF + k0 + c16);
        }
        CP_COMMIT();
    };

    load_stage(0, 0);
    load_stage(1, BK);

    for (int k = 0; k < NK; k++) {
        if (k + 1 < NK) CP_WAIT1(); else CP_WAIT0();
        __syncthreads();
        if (k + 2 < NK) load_stage((k + 2) % NSTAGE, (k + 2) * BK);

        int slot = k % NSTAGE;
        uint32_t Au = sm_u + slot * STG_H * 2;
        uint32_t Bu = Au + STA_H * 2;
#pragma unroll
        for (int c = 0; c < 4; c++) {
            int kc = c * 16;
            uint32_t a[2][4];
#pragma unroll
            for (int mi = 0; mi < 2; mi++)
                ldsm4(a[mi], Au + ((wm + mi * 16 + lrA) * PITCH + kc + kgA) * 2);
#pragma unroll
            for (int p = 0; p < 4; p++) {
                uint32_t b[4];
                ldsm4(b, Bu + ((wn + p * 16 + lrB) * PITCH + kc + kgB) * 2);
#pragma unroll
                for (int mi = 0; mi < 2; mi++) {
                    mma_f16(acc[mi][p * 2 + 0], a[mi], b[0], b[1]);
                    mma_f16(acc[mi][p * 2 + 1], a[mi], b[2], b[3]);
                }
            }
        }
    }

#pragma unroll
    for (int mi = 0; mi < 2; mi++) {
#pragma unroll
        for (int t2 = 0; t2 < 2; t2++) {
            int row = r0 + wm + mi * 16 + grp + t2 * 8;
            float w = g_wt[row];
            __half* op = g_oh + (size_t)row * DD + n0;
#pragma unroll
            for (int ni = 0; ni < 8; ni++) {
                __half2 v = __floats2half2_rn(acc[mi][ni][t2 * 2 + 0] * w,
                                              acc[mi][ni][t2 * 2 + 1] * w);
                *reinterpret_cast<__half2*>(op + wn + ni * 8 + qid * 2) = v;
            }
        }
    }
}

// ---------------------------------------------------------------------------
__global__ void combine_kernel(float* __restrict__ out) {
    const int NC8 = DD / 8;
    int idx = blockIdx.x * blockDim.x + threadIdx.x;
    int stride = gridDim.x * blockDim.x;
    for (int i = idx; i < NT * NC8; i += stride) {
        int t = i / NC8, c = i % NC8;
        int p0 = g_tpos[2 * t + 0], p1 = g_tpos[2 * t + 1];
        union { uint4 u; __half2 h[4]; } a, b;
        a.u = reinterpret_cast<const uint4*>(g_oh)[(size_t)p0 * NC8 + c];
        b.u = reinterpret_cast<const uint4*>(g_oh)[(size_t)p1 * NC8 + c];
        float4 r0, r1;
        float2 s, q;
        s = __half22float2(a.h[0]); q = __half22float2(b.h[0]);
        r0.x = s.x + q.x; r0.y = s.y + q.y;
        s = __half22float2(a.h[1]); q = __half22float2(b.h[1]);
        r0.z = s.x + q.x; r0.w = s.y + q.y;
        s = __half22float2(a.h[2]); q = __half22float2(b.h[2]);
        r1.x = s.x + q.x; r1.y = s.y + q.y;
        s = __half22float2(a.h[3]); q = __half22float2(b.h[3]);
        r1.z = s.x + q.x; r1.w = s.y + q.y;
        reinterpret_cast<float4*>(out)[(size_t)i * 2 + 0] = r0;
        reinterpret_cast<float4*>(out)[(size_t)i * 2 + 1] = r1;
    }
}

// ---------------------------------------------------------------------------
extern "C" void kernel_launch(void* const* d_in, const int* in_sizes, int n_in,
                              void* d_out, int out_size) {
    const float* x  = (const float*)d_in[0];
    const float* gw = (const float*)d_in[1];
    const float* w1 = (const float*)d_in[2];
    const float* w3 = (const float*)d_in[3];
    const float* w2 = (const float*)d_in[4];
    float* out = (float*)d_out;

    static cudaStream_t s_aux = nullptr;
    static cudaEvent_t ev_fork = nullptr, ev_w13 = nullptr, ev_w2 = nullptr;
    if (s_aux == nullptr) {
        cudaStreamCreateWithFlags(&s_aux, cudaStreamNonBlocking);
        cudaEventCreateWithFlags(&ev_fork, cudaEventDisableTiming);
        cudaEventCreateWithFlags(&ev_w13, cudaEventDisableTiming);
        cudaEventCreateWithFlags(&ev_w2, cudaEventDisableTiming);
        cudaFuncSetAttribute(ffn1_kernel, cudaFuncAttributeMaxDynamicSharedMemorySize, SMEM_BYTES);
        cudaFuncSetAttribute(ffn2_kernel, cudaFuncAttributeMaxDynamicSharedMemorySize, SMEM_BYTES);
    }

    cudaEventRecord(ev_fork, 0);
    cudaStreamWaitEvent(s_aux, ev_fork, 0);

    // Aux stream: x convert + weight transposes (independent of router chain).
    convert_x_kernel<<<2048, 256, 0, s_aux>>>(x);
    transpose_w13_kernel<<<dim3((DD / 64) * (FF / 32), 16), 256, 0, s_aux>>>(w1, w3);
    cudaEventRecord(ev_w13, s_aux);
    transpose_w2_kernel<<<dim3((FF / 64) * (DD / 32), 8), 256, 0, s_aux>>>(w2);
    cudaEventRecord(ev_w2, s_aux);

    // Main stream: routing chain.
    init_kernel<<<256, 256>>>();
    transpose_gw_kernel<<<32, 256>>>(gw);
    router_kernel<<<NT / 8, 256>>>(x);
    offsets_kernel<<<1, 1>>>();
    scatter_kernel<<<(NT + 255) / 256, 256>>>();

    cudaStreamWaitEvent(0, ev_w13, 0);
    ffn1_kernel<<<MTP * (FF / BN1), 256, SMEM_BYTES>>>();
    cudaStreamWaitEvent(0, ev_w2, 0);
    ffn2_kernel<<<MTP * (DD / BN2), 256, SMEM_BYTES>>>();
    combine_kernel<<<2048, 256>>>(out);
}